// round 2
// baseline (speedup 1.0000x reference)
#include <cuda_runtime.h>

// ---------------- problem constants ----------------
static constexpr int NB    = 16;
static constexpr int CIN   = 64;
static constexpr int COUT  = 64;
static constexpr int HH    = 192;
static constexpr int WW    = 192;
static constexpr int HW    = HH * WW;          // 36864
static constexpr int HID   = 17;
static constexpr int KDY   = 4;
static constexpr int NGRP  = 8;
static constexpr float TEMP = 30.0f;
static constexpr float NEG_SLOPE = 0.01f;

// ---------------- device scratch (no allocations allowed) ----------------
__device__ float g_pooled[NB][CIN];
__device__ float g_attn[NB][KDY];
__device__ float g_filters[(size_t)NB * COUT * CIN * 9];   // 9.4 MB
__device__ float g_mean[NB * NGRP];
__device__ float g_rstd[NB * NGRP];

// ---------------- stage 1: global average pool ----------------
__global__ void pool_kernel(const float* __restrict__ x) {
    int bc = blockIdx.x;                       // 0..1023  (b*64 + c)
    const float* p = x + (size_t)bc * HW;
    float s = 0.f;
    for (int i = threadIdx.x; i < HW; i += 256) s += p[i];
    __shared__ float sh[256];
    sh[threadIdx.x] = s;
    __syncthreads();
    for (int st = 128; st > 0; st >>= 1) {
        if (threadIdx.x < st) sh[threadIdx.x] += sh[threadIdx.x + st];
        __syncthreads();
    }
    if (threadIdx.x == 0) g_pooled[bc >> 6][bc & 63] = sh[0] * (1.0f / HW);
}

// ---------------- stage 2: attention MLP + softmax ----------------
__global__ void attn_kernel(const float* __restrict__ w1,
                            const float* __restrict__ w2,
                            const float* __restrict__ b2) {
    int b = threadIdx.x;
    if (b >= NB) return;
    float h[HID];
    #pragma unroll
    for (int j = 0; j < HID; j++) {
        float s = 0.f;
        for (int c = 0; c < CIN; c++) s += g_pooled[b][c] * w1[j * CIN + c];
        h[j] = fmaxf(s, 0.f);
    }
    float sc[KDY];
    float m = -1e30f;
    #pragma unroll
    for (int k = 0; k < KDY; k++) {
        float s = b2[k];
        for (int j = 0; j < HID; j++) s += h[j] * w2[k * HID + j];
        sc[k] = s / TEMP;
        m = fmaxf(m, sc[k]);
    }
    float tot = 0.f;
    #pragma unroll
    for (int k = 0; k < KDY; k++) { sc[k] = expf(sc[k] - m); tot += sc[k]; }
    #pragma unroll
    for (int k = 0; k < KDY; k++) g_attn[b][k] = sc[k] / tot;
}

// ---------------- stage 3: synthesize per-sample filters ----------------
// weights layout [K][COUT][CIN][3][3]; k-stride == COUT*CIN*9 == 36864
__global__ void filter_kernel(const float* __restrict__ w) {
    const int PER = COUT * CIN * 9;            // 36864
    int n = blockIdx.x * 256 + threadIdx.x;
    if (n >= NB * PER) return;
    int b = n / PER, r = n - b * PER;
    float a0 = g_attn[b][0], a1 = g_attn[b][1], a2 = g_attn[b][2], a3 = g_attn[b][3];
    g_filters[n] = a0 * w[r] + a1 * w[PER + r] + a2 * w[2 * PER + r] + a3 * w[3 * PER + r];
}

// ---------------- stage 4: per-sample 3x3 conv (fp32, f32x2 FMA) ----------------
// 32x32 output tile, 16 out-channels per block, 8-channel smem stages.
// Each thread: 4 pixel rows (ty, ty+8, ty+16, ty+24) x 16 couts = 32 f32x2 accums.
static constexpr int TW = 32;
static constexpr int TH = 32;
static constexpr int CHUNK = 8;
static constexpr int COB = 16;

typedef unsigned long long u64;

__device__ __forceinline__ u64 pack2(float v) {
    u64 r; unsigned u = __float_as_uint(v);
    asm("mov.b64 %0, {%1, %1};" : "=l"(r) : "r"(u));
    return r;
}
__device__ __forceinline__ void fma2(u64& d, u64 a, u64 b) {
    asm("fma.rn.f32x2 %0, %1, %2, %0;" : "+l"(d) : "l"(a), "l"(b));
}

__global__ __launch_bounds__(256, 2) void conv_kernel(const float* __restrict__ x,
                                                      float* __restrict__ y) {
    __shared__ float sx[CHUNK][TH + 2][TW + 2];                 // 8*34*34*4 = 36992 B
    __shared__ __align__(16) float sf[CHUNK][9][COB];           // 4608 B
    const int b   = blockIdx.z >> 2;
    const int cob = (blockIdx.z & 3) * COB;
    const int h0 = blockIdx.y * TH, w0 = blockIdx.x * TW;
    const int tid = threadIdx.x, tx = tid & 31, ty = tid >> 5;  // ty 0..7
    const float* xb = x + (size_t)b * CIN * HW;

    u64 acc[32];                                                 // [row r][q]
    #pragma unroll
    for (int i = 0; i < 32; i++) acc[i] = 0ull;

    #pragma unroll 1
    for (int c0 = 0; c0 < CIN; c0 += CHUNK) {
        __syncthreads();
        // stage input tile (with halo, zero-padded)
        for (int i = tid; i < CHUNK * (TH + 2) * (TW + 2); i += 256) {
            int ci  = i / ((TH + 2) * (TW + 2));
            int rem = i - ci * ((TH + 2) * (TW + 2));
            int r = rem / (TW + 2), cc = rem - r * (TW + 2);
            int hh = h0 + r - 1, ww = w0 + cc - 1;
            float v = 0.f;
            if (hh >= 0 && hh < HH && ww >= 0 && ww < WW)
                v = xb[(size_t)(c0 + ci) * HW + hh * WW + ww];
            sx[ci][r][cc] = v;
        }
        // stage filters: sf[ci][tap][co]
        for (int i = tid; i < CHUNK * 9 * COB; i += 256) {
            int ci  = i / (9 * COB);
            int rem = i - ci * (9 * COB);
            int tap = rem / COB, co = rem - tap * COB;
            sf[ci][tap][co] =
                g_filters[(((size_t)b * COUT + cob + co) * CIN + (c0 + ci)) * 9 + tap];
        }
        __syncthreads();

        #pragma unroll 1
        for (int ci = 0; ci < CHUNK; ci++) {
            #pragma unroll
            for (int tap = 0; tap < 9; tap++) {
                const int kh = tap / 3, kw = tap % 3;
                u64 xr[4];
                #pragma unroll
                for (int r = 0; r < 4; r++)
                    xr[r] = pack2(sx[ci][ty + 8 * r + kh][tx + kw]);
                const ulonglong2* fp = (const ulonglong2*)&sf[ci][tap][0];
                #pragma unroll
                for (int j = 0; j < 4; j++) {                    // LDS.128: couts 4j..4j+3
                    ulonglong2 f = fp[j];
                    #pragma unroll
                    for (int r = 0; r < 4; r++) {
                        fma2(acc[r * 8 + 2 * j],     xr[r], f.x);
                        fma2(acc[r * 8 + 2 * j + 1], xr[r], f.y);
                    }
                }
            }
        }
    }

    #pragma unroll
    for (int r = 0; r < 4; r++) {
        size_t base = ((size_t)b * COUT + cob) * HW
                    + (size_t)(h0 + ty + 8 * r) * WW + (w0 + tx);
        #pragma unroll
        for (int q = 0; q < 8; q++) {
            unsigned lo, hi;
            asm("mov.b64 {%0, %1}, %2;" : "=r"(lo), "=r"(hi) : "l"(acc[r * 8 + q]));
            y[base + (size_t)(2 * q) * HW]     = __uint_as_float(lo);
            y[base + (size_t)(2 * q + 1) * HW] = __uint_as_float(hi);
        }
    }
}

// ---------------- stage 5a: GroupNorm statistics (deterministic) ----------------
__global__ void gnstat_kernel(const float* __restrict__ y) {
    int bg = blockIdx.x;                        // b*8 + g, region is contiguous
    const float* p = y + (size_t)bg * 8 * HW;
    double s = 0.0, ss = 0.0;
    for (int i = threadIdx.x; i < 8 * HW; i += 256) {
        float v = p[i];
        s += v; ss += (double)v * v;
    }
    __shared__ double sh1[256], sh2[256];
    sh1[threadIdx.x] = s; sh2[threadIdx.x] = ss;
    __syncthreads();
    for (int st = 128; st > 0; st >>= 1) {
        if (threadIdx.x < st) {
            sh1[threadIdx.x] += sh1[threadIdx.x + st];
            sh2[threadIdx.x] += sh2[threadIdx.x + st];
        }
        __syncthreads();
    }
    if (threadIdx.x == 0) {
        const double N = 8.0 * HW;
        double mean = sh1[0] / N;
        double var  = sh2[0] / N - mean * mean;
        g_mean[bg] = (float)mean;
        g_rstd[bg] = (float)rsqrt(var + 1e-5);
    }
}

// ---------------- stage 5b: normalize + affine + LeakyReLU (in place) ----------------
__global__ void norm_kernel(float* __restrict__ y,
                            const float* __restrict__ gamma,
                            const float* __restrict__ beta) {
    size_t n = (size_t)blockIdx.x * 256 + threadIdx.x;
    if (n >= (size_t)NB * COUT * HW) return;
    int c  = (int)(n / HW) & 63;
    int bg = (int)(n / ((size_t)8 * HW));       // = b*8 + c/8
    float v = y[n];
    float t = (v - g_mean[bg]) * g_rstd[bg] * gamma[c] + beta[c];
    y[n] = t >= 0.f ? t : NEG_SLOPE * t;
}

// ---------------- launch ----------------
extern "C" void kernel_launch(void* const* d_in, const int* in_sizes, int n_in,
                              void* d_out, int out_size) {
    const float* x     = (const float*)d_in[0];
    const float* w1    = (const float*)d_in[1];
    const float* w2    = (const float*)d_in[2];
    const float* b2    = (const float*)d_in[3];
    const float* w     = (const float*)d_in[4];
    const float* gamma = (const float*)d_in[5];
    const float* beta  = (const float*)d_in[6];
    float* y = (float*)d_out;

    pool_kernel<<<NB * CIN, 256>>>(x);
    attn_kernel<<<1, 32>>>(w1, w2, b2);
    filter_kernel<<<(NB * COUT * CIN * 9 + 255) / 256, 256>>>(w);

    dim3 g(WW / TW, HH / TH, NB * 4);
    conv_kernel<<<g, 256>>>(x, y);

    gnstat_kernel<<<NB * NGRP, 256>>>(y);
    norm_kernel<<<(int)(((size_t)NB * COUT * HW + 255) / 256), 256>>>(y, gamma, beta);
}

// round 3
// speedup vs baseline: 1.8716x; 1.8716x over previous
#include <cuda_runtime.h>

// ---------------- problem constants ----------------
static constexpr int NB    = 16;
static constexpr int CIN   = 64;
static constexpr int COUT  = 64;
static constexpr int HH    = 192;
static constexpr int WW    = 192;
static constexpr int HW    = HH * WW;          // 36864
static constexpr int HID   = 17;
static constexpr int KDY   = 4;
static constexpr int NGRP  = 8;
static constexpr float TEMP = 30.0f;
static constexpr float NEG_SLOPE = 0.01f;

// ---------------- device scratch (no allocations allowed) ----------------
__device__ float g_pooled[NB][CIN];
__device__ float g_attn[NB][KDY];
__device__ float g_filters[(size_t)NB * COUT * CIN * 9];   // 2.36 MB
__device__ float g_mean[NB * NGRP];
__device__ float g_rstd[NB * NGRP];

// ---------------- stage 1: global average pool (float4) ----------------
__global__ void pool_kernel(const float* __restrict__ x) {
    int bc = blockIdx.x;                       // 0..1023  (b*64 + c)
    const float4* p = (const float4*)(x + (size_t)bc * HW);
    float s = 0.f;
    for (int i = threadIdx.x; i < HW / 4; i += 256) {
        float4 v = p[i];
        s += (v.x + v.y) + (v.z + v.w);
    }
    __shared__ float sh[256];
    sh[threadIdx.x] = s;
    __syncthreads();
    for (int st = 128; st > 0; st >>= 1) {
        if (threadIdx.x < st) sh[threadIdx.x] += sh[threadIdx.x + st];
        __syncthreads();
    }
    if (threadIdx.x == 0) g_pooled[bc >> 6][bc & 63] = sh[0] * (1.0f / HW);
}

// ---------------- stage 2: attention MLP + softmax ----------------
__global__ void attn_kernel(const float* __restrict__ w1,
                            const float* __restrict__ w2,
                            const float* __restrict__ b2) {
    int b = threadIdx.x;
    if (b >= NB) return;
    float h[HID];
    #pragma unroll
    for (int j = 0; j < HID; j++) {
        float s = 0.f;
        for (int c = 0; c < CIN; c++) s += g_pooled[b][c] * w1[j * CIN + c];
        h[j] = fmaxf(s, 0.f);
    }
    float sc[KDY];
    float m = -1e30f;
    #pragma unroll
    for (int k = 0; k < KDY; k++) {
        float s = b2[k];
        for (int j = 0; j < HID; j++) s += h[j] * w2[k * HID + j];
        sc[k] = s / TEMP;
        m = fmaxf(m, sc[k]);
    }
    float tot = 0.f;
    #pragma unroll
    for (int k = 0; k < KDY; k++) { sc[k] = expf(sc[k] - m); tot += sc[k]; }
    #pragma unroll
    for (int k = 0; k < KDY; k++) g_attn[b][k] = sc[k] / tot;
}

// ---------------- stage 3: synthesize per-sample filters (float4) ----------------
// weights layout [K][COUT][CIN][3][3]; k-stride == COUT*CIN*9 == 36864 elements
__global__ void filter_kernel(const float* __restrict__ w) {
    const int PER4 = COUT * CIN * 9 / 4;       // 9216 float4 per sample
    int n = blockIdx.x * 256 + threadIdx.x;
    if (n >= NB * PER4) return;
    int b = n / PER4, r = n - b * PER4;
    float a0 = g_attn[b][0], a1 = g_attn[b][1], a2 = g_attn[b][2], a3 = g_attn[b][3];
    const float4* w4 = (const float4*)w;
    float4 v0 = w4[r], v1 = w4[PER4 + r], v2 = w4[2 * PER4 + r], v3 = w4[3 * PER4 + r];
    float4 o;
    o.x = a0 * v0.x + a1 * v1.x + a2 * v2.x + a3 * v3.x;
    o.y = a0 * v0.y + a1 * v1.y + a2 * v2.y + a3 * v3.y;
    o.z = a0 * v0.z + a1 * v1.z + a2 * v2.z + a3 * v3.z;
    o.w = a0 * v0.w + a1 * v1.w + a2 * v2.w + a3 * v3.w;
    ((float4*)g_filters)[n] = o;
}

// ---------------- stage 4: per-sample 3x3 conv (fp32, f32x2 FMA) ----------------
// Round-1 shape: 32x16 tile, 16 couts/block, 16-channel stages, 2 rows/thread.
// Only change vs R1: filter reads are LDS.128 (4 broadcasts/tap, was 8 LDS.64).
static constexpr int TW = 32;
static constexpr int TH = 16;
static constexpr int CHUNK = 16;
static constexpr int COB = 16;

typedef unsigned long long u64;

__device__ __forceinline__ u64 pack2(float v) {
    u64 r; unsigned u = __float_as_uint(v);
    asm("mov.b64 %0, {%1, %1};" : "=l"(r) : "r"(u));
    return r;
}
__device__ __forceinline__ void fma2(u64& d, u64 a, u64 b) {
    asm("fma.rn.f32x2 %0, %1, %2, %0;" : "+l"(d) : "l"(a), "l"(b));
}

__global__ __launch_bounds__(256) void conv_kernel(const float* __restrict__ x,
                                                   float* __restrict__ y) {
    __shared__ float sx[CHUNK][TH + 2][TW + 2];                 // 39168 B
    __shared__ __align__(16) float sf[CHUNK][9][COB];           //  9216 B
    const int b   = blockIdx.z >> 2;
    const int cob = (blockIdx.z & 3) * COB;
    const int h0 = blockIdx.y * TH, w0 = blockIdx.x * TW;
    const int tid = threadIdx.x, tx = tid & 31, ty = tid >> 5;  // ty 0..7
    const float* xb = x + (size_t)b * CIN * HW;

    u64 acc[16];
    #pragma unroll
    for (int i = 0; i < 16; i++) acc[i] = 0ull;

    for (int c0 = 0; c0 < CIN; c0 += CHUNK) {
        __syncthreads();
        // stage input tile (with halo, zero-padded)
        for (int i = tid; i < CHUNK * (TH + 2) * (TW + 2); i += 256) {
            int ci  = i / ((TH + 2) * (TW + 2));
            int rem = i - ci * ((TH + 2) * (TW + 2));
            int r = rem / (TW + 2), cc = rem - r * (TW + 2);
            int hh = h0 + r - 1, ww = w0 + cc - 1;
            float v = 0.f;
            if (hh >= 0 && hh < HH && ww >= 0 && ww < WW)
                v = xb[(size_t)(c0 + ci) * HW + hh * WW + ww];
            sx[ci][r][cc] = v;
        }
        // stage filters: sf[ci][tap][co]
        for (int i = tid; i < CHUNK * 9 * COB; i += 256) {
            int ci  = i / (9 * COB);
            int rem = i - ci * (9 * COB);
            int tap = rem / COB, co = rem - tap * COB;
            sf[ci][tap][co] =
                g_filters[(((size_t)b * COUT + cob + co) * CIN + (c0 + ci)) * 9 + tap];
        }
        __syncthreads();

        #pragma unroll 1
        for (int ci = 0; ci < CHUNK; ci++) {
            #pragma unroll
            for (int tap = 0; tap < 9; tap++) {
                const int kh = tap / 3, kw = tap % 3;
                u64 x0 = pack2(sx[ci][ty + kh][tx + kw]);
                u64 x1 = pack2(sx[ci][ty + 8 + kh][tx + kw]);
                const ulonglong2* fp = (const ulonglong2*)&sf[ci][tap][0];
                #pragma unroll
                for (int j = 0; j < 4; j++) {                  // LDS.128: couts 4j..4j+3
                    ulonglong2 f = fp[j];
                    fma2(acc[2 * j],         x0, f.x);
                    fma2(acc[2 * j + 1],     x0, f.y);
                    fma2(acc[8 + 2 * j],     x1, f.x);
                    fma2(acc[8 + 2 * j + 1], x1, f.y);
                }
            }
        }
    }

    size_t base = ((size_t)b * COUT + cob) * HW + (size_t)(h0 + ty) * WW + (w0 + tx);
    #pragma unroll
    for (int q = 0; q < 8; q++) {
        unsigned lo, hi;
        asm("mov.b64 {%0, %1}, %2;" : "=r"(lo), "=r"(hi) : "l"(acc[q]));
        y[base + (size_t)(2 * q) * HW]     = __uint_as_float(lo);
        y[base + (size_t)(2 * q + 1) * HW] = __uint_as_float(hi);
        asm("mov.b64 {%0, %1}, %2;" : "=r"(lo), "=r"(hi) : "l"(acc[8 + q]));
        y[base + (size_t)(2 * q) * HW + 8 * WW]     = __uint_as_float(lo);
        y[base + (size_t)(2 * q + 1) * HW + 8 * WW] = __uint_as_float(hi);
    }
}

// ---------------- stage 5a: GroupNorm statistics (float4, fp32 partials) ----------------
__global__ void gnstat_kernel(const float* __restrict__ y) {
    int bg = blockIdx.x;                        // b*8 + g, region is contiguous
    const float4* p = (const float4*)(y + (size_t)bg * 8 * HW);
    float s = 0.f, ss = 0.f;
    for (int i = threadIdx.x; i < 8 * HW / 4; i += 256) {
        float4 v = p[i];
        s  += (v.x + v.y) + (v.z + v.w);
        ss += (v.x * v.x + v.y * v.y) + (v.z * v.z + v.w * v.w);
    }
    __shared__ float sh1[256], sh2[256];
    sh1[threadIdx.x] = s; sh2[threadIdx.x] = ss;
    __syncthreads();
    for (int st = 128; st > 0; st >>= 1) {
        if (threadIdx.x < st) {
            sh1[threadIdx.x] += sh1[threadIdx.x + st];
            sh2[threadIdx.x] += sh2[threadIdx.x + st];
        }
        __syncthreads();
    }
    if (threadIdx.x == 0) {
        const double N = 8.0 * HW;
        double mean = (double)sh1[0] / N;
        double var  = (double)sh2[0] / N - mean * mean;
        g_mean[bg] = (float)mean;
        g_rstd[bg] = (float)rsqrt(var + 1e-5);
    }
}

// ---------------- stage 5b: normalize + affine + LeakyReLU (float4, div-free) ----------------
__global__ void norm_kernel(float* __restrict__ y,
                            const float* __restrict__ gamma,
                            const float* __restrict__ beta) {
    // grid: (HW/1024, NB*COUT); block 256; float4 per thread
    int bc = blockIdx.y;                        // b*64 + c
    int c  = bc & 63;
    int bg = bc >> 3;                           // b*8 + c/8
    float mu = g_mean[bg], rs = g_rstd[bg];
    float ga = gamma[c] * rs;
    float be = beta[c] - mu * ga;
    float4* p = (float4*)(y + (size_t)bc * HW) + blockIdx.x * 256 + threadIdx.x;
    float4 v = *p;
    v.x = fmaf(v.x, ga, be); v.x = v.x >= 0.f ? v.x : NEG_SLOPE * v.x;
    v.y = fmaf(v.y, ga, be); v.y = v.y >= 0.f ? v.y : NEG_SLOPE * v.y;
    v.z = fmaf(v.z, ga, be); v.z = v.z >= 0.f ? v.z : NEG_SLOPE * v.z;
    v.w = fmaf(v.w, ga, be); v.w = v.w >= 0.f ? v.w : NEG_SLOPE * v.w;
    *p = v;
}

// ---------------- launch ----------------
extern "C" void kernel_launch(void* const* d_in, const int* in_sizes, int n_in,
                              void* d_out, int out_size) {
    const float* x     = (const float*)d_in[0];
    const float* w1    = (const float*)d_in[1];
    const float* w2    = (const float*)d_in[2];
    const float* b2    = (const float*)d_in[3];
    const float* w     = (const float*)d_in[4];
    const float* gamma = (const float*)d_in[5];
    const float* beta  = (const float*)d_in[6];
    float* y = (float*)d_out;

    pool_kernel<<<NB * CIN, 256>>>(x);
    attn_kernel<<<1, 32>>>(w1, w2, b2);
    filter_kernel<<<(NB * COUT * CIN * 9 / 4 + 255) / 256, 256>>>(w);

    dim3 g(WW / TW, HH / TH, NB * 4);
    conv_kernel<<<g, 256>>>(x, y);

    gnstat_kernel<<<NB * NGRP, 256>>>(y);
    dim3 gn(HW / 1024, NB * COUT);
    norm_kernel<<<gn, 256>>>(y, gamma, beta);
}